// round 13
// baseline (speedup 1.0000x reference)
#include <cuda_runtime.h>
#include <cuda.h>
#include <cstdint>
#include <cstddef>

// out[b,t,k,n,o] = sum_i x[b,t,n,i] * Wqkv[k, perm[phase,k,n], i, o]
// 64 GEMMs of [2048,1024]x[1024,192] fp32. tf32 mma.sync.m16n8k8 (cvt.rna).
// R13: R12's 3-CTA/SM experiment with the pipeline protocol FIXED: with
// NSTAGE=2 the prologue prefetches exactly ONE chunk (chunk 0) and the loop
// issues cc=c+1. (R12 double-issued chunk 1 -> barrier phase corruption.)

namespace {

constexpr int N_ = 16, IN_ = 1024, K_ = 4, D3_ = 192;
constexpr int M_TOTAL = 2048;
constexpr int TILE_M = 128;
constexpr int KC = 32;                     // K per chunk
constexpr int NCHUNK = IN_ / KC;           // 32
constexpr int NSTAGE = 2;
constexpr int NTHREADS = 128;

constexpr int B_BOX_O = 40;                // 160B pitch -> 8-bank stagger/row
constexpr int B_BLK = B_BOX_O * KC * 4;    // 5120 bytes per o-block
constexpr int STAGE_BASE = 1024;
constexpr int A_SZ = TILE_M * KC * 4;      // 16384
constexpr int B_SZ = 3 * B_BLK;            // 15360
constexpr int STAGE_SZ = A_SZ + B_SZ;      // 31744 (= 31*1024, keeps A aligned)
constexpr int SMEM_TOTAL = STAGE_BASE + NSTAGE * STAGE_SZ;  // 64512 (x3 CTA fits)
constexpr uint32_t CHUNK_TX = (uint32_t)STAGE_SZ;

__device__ __forceinline__ uint32_t smem_u32(const void* p) {
    uint32_t a;
    asm("{ .reg .u64 t; cvta.to.shared.u64 t, %1; cvt.u32.u64 %0, t; }"
        : "=r"(a) : "l"(p));
    return a;
}

__device__ __forceinline__ void mbar_init(uint32_t a, uint32_t cnt) {
    asm volatile("mbarrier.init.shared.b64 [%0], %1;" :: "r"(a), "r"(cnt) : "memory");
}
__device__ __forceinline__ void mbar_arrive(uint32_t a) {
    asm volatile("mbarrier.arrive.shared.b64 _, [%0];" :: "r"(a) : "memory");
}
__device__ __forceinline__ void mbar_expect_tx(uint32_t a, uint32_t bytes) {
    asm volatile("mbarrier.arrive.expect_tx.shared.b64 _, [%0], %1;"
                 :: "r"(a), "r"(bytes) : "memory");
}
__device__ __forceinline__ void mbar_wait(uint32_t a, uint32_t parity) {
    uint32_t done;
    asm volatile(
        "{\n\t.reg .pred p;\n\t"
        "mbarrier.try_wait.parity.acquire.cta.shared::cta.b64 p, [%1], %2;\n\t"
        "selp.b32 %0, 1, 0, p;\n\t}"
        : "=r"(done) : "r"(a), "r"(parity) : "memory");
    if (!done) {
        asm volatile(
            "{\n\t.reg .pred P1;\n\t"
            "WL_%=:\n\t"
            "mbarrier.try_wait.parity.acquire.cta.shared::cta.b64 P1, [%0], %1, 0x989680;\n\t"
            "@P1 bra.uni WD_%=;\n\t"
            "bra.uni WL_%=;\n\t"
            "WD_%=:\n\t}"
            :: "r"(a), "r"(parity) : "memory");
    }
}

__device__ __forceinline__ void tma3(uint32_t dst, const CUtensorMap* map,
                                     int c0, int c1, int c2, uint32_t mbar) {
    asm volatile(
        "cp.async.bulk.tensor.3d.shared::cta.global.tile.mbarrier::complete_tx::bytes "
        "[%0], [%1, {%2, %3, %4}], [%5];"
        :: "r"(dst), "l"(map), "r"(c0), "r"(c1), "r"(c2), "r"(mbar) : "memory");
}

__device__ __forceinline__ uint32_t f2tf32(float f) {
    uint32_t r;
    asm("cvt.rna.tf32.f32 %0, %1;" : "=r"(r) : "f"(f));
    return r;
}
__device__ __forceinline__ uint32_t lds32(const char* p) {
    return *(const uint32_t*)p;
}

__device__ __forceinline__ void mma_tf32(float* d,
                                         uint32_t a0, uint32_t a1,
                                         uint32_t a2, uint32_t a3,
                                         uint32_t b0, uint32_t b1) {
    asm volatile(
        "mma.sync.aligned.m16n8k8.row.col.f32.tf32.tf32.f32 "
        "{%0,%1,%2,%3}, {%4,%5,%6,%7}, {%8,%9}, {%0,%1,%2,%3};"
        : "+f"(d[0]), "+f"(d[1]), "+f"(d[2]), "+f"(d[3])
        : "r"(a0), "r"(a1), "r"(a2), "r"(a3), "r"(b0), "r"(b1));
}

} // namespace

__global__ void __launch_bounds__(NTHREADS, 3)
qkv_tma_kernel(const int* __restrict__ perm32,
               const int* __restrict__ phase_p,
               float* __restrict__ out,
               const __grid_constant__ CUtensorMap tmA,
               const __grid_constant__ CUtensorMap tmB)
{
    extern __shared__ char sm[];
    const uint32_t smb = smem_u32(sm);
    const int tid = threadIdx.x;
    const int wid = tid >> 5;
    const int lid = tid & 31;
    const int gid = lid >> 2;               // groupID 0..7
    const int tg  = lid & 3;                // threadID_in_group 0..3

    const int tile_m = blockIdx.x;          // 0..15
    const int yid    = blockIdx.y;          // 0..127
    const int pair   = yid >> 1;            // 0..63
    const int half   = yid & 1;             // N-half: o base = half*96
    const int n = pair >> 2;
    const int k = pair & 3;
    const int m0 = tile_m * TILE_M;

    // ---- dtype-robust perm read ----
    const int phase = __ldg(phase_p) & 0xFFFF;
    const bool is64 = (__ldg(perm32 + 1) == 0) &&
                      (__ldg(perm32 + 3) == 0) &&
                      (__ldg(perm32 + 5) == 0);
    const int pidx = phase * (K_ * N_) + k * N_ + n;
    int pm = __ldg(perm32 + (is64 ? 2 * pidx : pidx));
    pm &= 15;
    const int kn = k * N_ + pm;
    const int o_cta = half * 96;

    // warp grid 2 (m) x 2 (n): warp tile 64 x 48
    const int wm = wid >> 1;
    const int wn = wid & 1;
    const int m_base = wm * 64;
    const int n_base = wn * 48;              // local o within CTA's 96

    // SW128 per-thread xor mask (A only; B unswizzled, pitch-staggered)
    const uint32_t mAx = (uint32_t)gid << 4;

    float acc[4][6][4];
    #pragma unroll
    for (int mt = 0; mt < 4; ++mt)
        #pragma unroll
        for (int nt = 0; nt < 6; ++nt)
            #pragma unroll
            for (int r = 0; r < 4; ++r) acc[mt][nt][r] = 0.0f;

    if (tid == 0) {
        #pragma unroll
        for (int s = 0; s < NSTAGE; ++s) {
            mbar_init(smb + s * 8, 1);              // full[s] (expect_tx)
            mbar_init(smb + 64 + s * 8, NTHREADS);  // empty[s]
        }
    }
    __syncthreads();

    auto issue = [&](int cc, int s) {
        const uint32_t mb = smb + s * 8;
        const uint32_t st = smb + STAGE_BASE + s * STAGE_SZ;
        const int i0 = cc * KC;
        mbar_expect_tx(mb, CHUNK_TX);
        tma3(st, &tmA, i0, n, m0, mb);               // A [32 i][1 n][128 m] SW128
        #pragma unroll
        for (int ob = 0; ob < 3; ++ob)               // B [40 o][32 i] unswizzled
            tma3(st + A_SZ + ob * B_BLK, &tmB, o_cta + ob * 32, i0, kn, mb);
    };

    // Prologue prefetches exactly NSTAGE-1 = 1 chunk; loop issues cc = c+1.
    if (tid == 0) { issue(0, 0); }

    // B per-thread base: row tg (160B/row), col gid
    const uint32_t bThr = (uint32_t)(tg * 160 + gid * 4);

    for (int c = 0; c < NCHUNK; ++c) {
        const int cs = c & 1;
        const uint32_t cp = (uint32_t)((c >> 1) & 1);
        if (tid == 0) {
            const int cc = c + NSTAGE - 1;           // c + 1
            if (cc < NCHUNK) {
                const int ps = cc & 1;
                const uint32_t ppar = (uint32_t)((cc >> 1) & 1);
                if (cc >= NSTAGE)                    // wait consumers of cc-2
                    mbar_wait(smb + 64 + ps * 8, ppar ^ 1);
                issue(cc, ps);
            }
        }
        mbar_wait(smb + cs * 8, cp);

        const char* sa  = sm + STAGE_BASE + cs * STAGE_SZ;
        const char* sbb = sa + A_SZ;

        #pragma unroll
        for (int ks = 0; ks < 4; ++ks) {
            const uint32_t i4 = (uint32_t)(ks * 32 + tg * 4);
            uint32_t af[4][4];
            #pragma unroll
            for (int mt = 0; mt < 4; ++mt) {
                const char* p = sa + (m_base + mt * 16 + gid) * 128;
                af[mt][0] = f2tf32(__uint_as_float(lds32(p + (i4 ^ mAx))));
                af[mt][1] = f2tf32(__uint_as_float(lds32(p + 1024 + (i4 ^ mAx))));
                af[mt][2] = f2tf32(__uint_as_float(lds32(p + ((i4 + 16) ^ mAx))));
                af[mt][3] = f2tf32(__uint_as_float(lds32(p + 1024 + ((i4 + 16) ^ mAx))));
            }
            #pragma unroll
            for (int nt = 0; nt < 6; ++nt) {
                const int oabs = n_base + nt * 8;          // local, [0,96)
                const char* q = sbb + (oabs >> 5) * B_BLK + ks * (8 * 160) + bThr
                              + (oabs & 31) * 4;
                const uint32_t b0 = f2tf32(__uint_as_float(lds32(q)));
                const uint32_t b1 = f2tf32(__uint_as_float(lds32(q + 4 * 160)));
                #pragma unroll
                for (int mt = 0; mt < 4; ++mt)
                    mma_tf32(acc[mt][nt],
                             af[mt][0], af[mt][1], af[mt][2], af[mt][3], b0, b1);
            }
        }
        mbar_arrive(smb + 64 + cs * 8);
    }

    // ---- epilogue ----
    #pragma unroll
    for (int mt = 0; mt < 4; ++mt) {
        const size_t r0 = (size_t)(m0 + m_base + mt * 16 + gid);
        const size_t r1 = r0 + 8;
        float* ob0 = out + (((r0 * K_ + (size_t)k) * N_) + (size_t)n) * (size_t)D3_;
        float* ob1 = out + (((r1 * K_ + (size_t)k) * N_) + (size_t)n) * (size_t)D3_;
        #pragma unroll
        for (int nt = 0; nt < 6; ++nt) {
            const int col = o_cta + n_base + nt * 8 + tg * 2;
            *(float2*)(ob0 + col) = make_float2(acc[mt][nt][0], acc[mt][nt][1]);
            *(float2*)(ob1 + col) = make_float2(acc[mt][nt][2], acc[mt][nt][3]);
        }
    }
}

extern "C" void kernel_launch(void* const* d_in, const int* in_sizes, int n_in,
                              void* d_out, int out_size) {
    const float* x     = (const float*)d_in[0];
    const float* Wqkv  = (const float*)d_in[1];
    const int* perm32  = (const int*)d_in[2];
    // d_in[3] = invperm (unused)
    const int* phase   = (const int*)d_in[4];
    float* out         = (float*)d_out;

    typedef CUresult (*EncFn)(CUtensorMap*, CUtensorMapDataType, cuuint32_t, void*,
                              const cuuint64_t*, const cuuint64_t*,
                              const cuuint32_t*, const cuuint32_t*,
                              CUtensorMapInterleave, CUtensorMapSwizzle,
                              CUtensorMapL2promotion, CUtensorMapFloatOOBfill);
    EncFn enc = nullptr;
    cudaDriverEntryPointQueryResult qst;
#if CUDART_VERSION >= 12050
    cudaGetDriverEntryPointByVersion("cuTensorMapEncodeTiled", (void**)&enc,
                                     12000, cudaEnableDefault, &qst);
#else
    cudaGetDriverEntryPoint("cuTensorMapEncodeTiled", (void**)&enc,
                            cudaEnableDefault, &qst);
#endif
    CUtensorMap tmA, tmB;
    {
        cuuint64_t dims[3]    = {(cuuint64_t)IN_, (cuuint64_t)N_, (cuuint64_t)M_TOTAL};
        cuuint64_t strides[2] = {(cuuint64_t)IN_ * 4, (cuuint64_t)N_ * IN_ * 4};
        cuuint32_t box[3]     = {32, 1, (cuuint32_t)TILE_M};
        cuuint32_t es[3]      = {1, 1, 1};
        enc(&tmA, CU_TENSOR_MAP_DATA_TYPE_FLOAT32, 3, (void*)x,
            dims, strides, box, es,
            CU_TENSOR_MAP_INTERLEAVE_NONE, CU_TENSOR_MAP_SWIZZLE_128B,
            CU_TENSOR_MAP_L2_PROMOTION_L2_128B, CU_TENSOR_MAP_FLOAT_OOB_FILL_NONE);
    }
    {
        cuuint64_t dims[3]    = {(cuuint64_t)D3_, (cuuint64_t)IN_, (cuuint64_t)(K_ * N_)};
        cuuint64_t strides[2] = {(cuuint64_t)D3_ * 4, (cuuint64_t)IN_ * D3_ * 4};
        cuuint32_t box[3]     = {(cuuint32_t)B_BOX_O, 32, 1};
        cuuint32_t es[3]      = {1, 1, 1};
        enc(&tmB, CU_TENSOR_MAP_DATA_TYPE_FLOAT32, 3, (void*)Wqkv,
            dims, strides, box, es,
            CU_TENSOR_MAP_INTERLEAVE_NONE, CU_TENSOR_MAP_SWIZZLE_NONE,
            CU_TENSOR_MAP_L2_PROMOTION_L2_128B, CU_TENSOR_MAP_FLOAT_OOB_FILL_NONE);
    }

    cudaFuncSetAttribute(qkv_tma_kernel,
                         cudaFuncAttributeMaxDynamicSharedMemorySize, SMEM_TOTAL);
    dim3 grid(M_TOTAL / TILE_M, (K_ * N_) * 2);   // (16, 128)
    qkv_tma_kernel<<<grid, NTHREADS, SMEM_TOTAL>>>(perm32, phase, out, tmA, tmB);
}

// round 14
// speedup vs baseline: 1.1118x; 1.1118x over previous
#include <cuda_runtime.h>
#include <cuda.h>
#include <cstdint>
#include <cstddef>

// out[b,t,k,n,o] = sum_i x[b,t,n,i] * Wqkv[k, perm[phase,k,n], i, o]
// 64 GEMMs of [2048,1024]x[1024,192] fp32. tf32 mma.sync.m16n8k8.
// R14: R11 (296.9us) with cvt.rna.tf32 (F2FP, ~20cyc) replaced by an integer
// half-ulp add (bits + 0x1000, IADD lat 4): tf32 HW reads only the top 19
// bits, so +half-ulp-then-truncate == round-to-nearest. Shortens the
// LDS->convert->MMA operand chain by ~16 cyc per fragment.

namespace {

constexpr int N_ = 16, IN_ = 1024, K_ = 4, D3_ = 192;
constexpr int M_TOTAL = 2048;
constexpr int TILE_M = 128;
constexpr int KC = 32;                     // K per chunk
constexpr int NCHUNK = IN_ / KC;           // 32
constexpr int NSTAGE = 3;
constexpr int NTHREADS = 128;

constexpr int B_BOX_O = 40;                // 160B pitch -> 8-bank stagger/row
constexpr int B_BLK = B_BOX_O * KC * 4;    // 5120 bytes per o-block
constexpr int STAGE_BASE = 1024;
constexpr int A_SZ = TILE_M * KC * 4;      // 16384
constexpr int B_SZ = 3 * B_BLK;            // 15360
constexpr int STAGE_SZ = A_SZ + B_SZ;      // 31744 (= 31*1024, keeps A aligned)
constexpr int SMEM_TOTAL = STAGE_BASE + NSTAGE * STAGE_SZ;  // 96256 (x2 CTA fits)
constexpr uint32_t CHUNK_TX = (uint32_t)STAGE_SZ;

__device__ __forceinline__ uint32_t smem_u32(const void* p) {
    uint32_t a;
    asm("{ .reg .u64 t; cvta.to.shared.u64 t, %1; cvt.u32.u64 %0, t; }"
        : "=r"(a) : "l"(p));
    return a;
}

__device__ __forceinline__ void mbar_init(uint32_t a, uint32_t cnt) {
    asm volatile("mbarrier.init.shared.b64 [%0], %1;" :: "r"(a), "r"(cnt) : "memory");
}
__device__ __forceinline__ void mbar_arrive(uint32_t a) {
    asm volatile("mbarrier.arrive.shared.b64 _, [%0];" :: "r"(a) : "memory");
}
__device__ __forceinline__ void mbar_expect_tx(uint32_t a, uint32_t bytes) {
    asm volatile("mbarrier.arrive.expect_tx.shared.b64 _, [%0], %1;"
                 :: "r"(a), "r"(bytes) : "memory");
}
__device__ __forceinline__ void mbar_wait(uint32_t a, uint32_t parity) {
    uint32_t done;
    asm volatile(
        "{\n\t.reg .pred p;\n\t"
        "mbarrier.try_wait.parity.acquire.cta.shared::cta.b64 p, [%1], %2;\n\t"
        "selp.b32 %0, 1, 0, p;\n\t}"
        : "=r"(done) : "r"(a), "r"(parity) : "memory");
    if (!done) {
        asm volatile(
            "{\n\t.reg .pred P1;\n\t"
            "WL_%=:\n\t"
            "mbarrier.try_wait.parity.acquire.cta.shared::cta.b64 P1, [%0], %1, 0x989680;\n\t"
            "@P1 bra.uni WD_%=;\n\t"
            "bra.uni WL_%=;\n\t"
            "WD_%=:\n\t}"
            :: "r"(a), "r"(parity) : "memory");
    }
}

__device__ __forceinline__ void tma3(uint32_t dst, const CUtensorMap* map,
                                     int c0, int c1, int c2, uint32_t mbar) {
    asm volatile(
        "cp.async.bulk.tensor.3d.shared::cta.global.tile.mbarrier::complete_tx::bytes "
        "[%0], [%1, {%2, %3, %4}], [%5];"
        :: "r"(dst), "l"(map), "r"(c0), "r"(c1), "r"(c2), "r"(mbar) : "memory");
}

// round-to-nearest tf32 via integer half-ulp add (replaces cvt.rna, ~20cyc
// F2FP, with a 4cyc IADD; HW ignores the low 13 bits of a tf32 operand).
__device__ __forceinline__ uint32_t tf32r(uint32_t bits) {
    return bits + 0x1000u;
}
__device__ __forceinline__ uint32_t lds32(const char* p) {
    return *(const uint32_t*)p;
}

__device__ __forceinline__ void mma_tf32(float* d,
                                         uint32_t a0, uint32_t a1,
                                         uint32_t a2, uint32_t a3,
                                         uint32_t b0, uint32_t b1) {
    asm volatile(
        "mma.sync.aligned.m16n8k8.row.col.f32.tf32.tf32.f32 "
        "{%0,%1,%2,%3}, {%4,%5,%6,%7}, {%8,%9}, {%0,%1,%2,%3};"
        : "+f"(d[0]), "+f"(d[1]), "+f"(d[2]), "+f"(d[3])
        : "r"(a0), "r"(a1), "r"(a2), "r"(a3), "r"(b0), "r"(b1));
}

} // namespace

__global__ void __launch_bounds__(NTHREADS, 2)
qkv_tma_kernel(const int* __restrict__ perm32,
               const int* __restrict__ phase_p,
               float* __restrict__ out,
               const __grid_constant__ CUtensorMap tmA,
               const __grid_constant__ CUtensorMap tmB)
{
    extern __shared__ char sm[];
    const uint32_t smb = smem_u32(sm);
    const int tid = threadIdx.x;
    const int wid = tid >> 5;
    const int lid = tid & 31;
    const int gid = lid >> 2;               // groupID 0..7
    const int tg  = lid & 3;                // threadID_in_group 0..3

    const int tile_m = blockIdx.x;          // 0..15
    const int yid    = blockIdx.y;          // 0..127
    const int pair   = yid >> 1;            // 0..63
    const int half   = yid & 1;             // N-half: o base = half*96
    const int n = pair >> 2;
    const int k = pair & 3;
    const int m0 = tile_m * TILE_M;

    // ---- dtype-robust perm read ----
    const int phase = __ldg(phase_p) & 0xFFFF;
    const bool is64 = (__ldg(perm32 + 1) == 0) &&
                      (__ldg(perm32 + 3) == 0) &&
                      (__ldg(perm32 + 5) == 0);
    const int pidx = phase * (K_ * N_) + k * N_ + n;
    int pm = __ldg(perm32 + (is64 ? 2 * pidx : pidx));
    pm &= 15;
    const int kn = k * N_ + pm;
    const int o_cta = half * 96;

    // warp grid 2 (m) x 2 (n): warp tile 64 x 48
    const int wm = wid >> 1;
    const int wn = wid & 1;
    const int m_base = wm * 64;
    const int n_base = wn * 48;              // local o within CTA's 96

    // SW128 per-thread xor mask (A only; B unswizzled, pitch-staggered)
    const uint32_t mAx = (uint32_t)gid << 4;

    float acc[4][6][4];
    #pragma unroll
    for (int mt = 0; mt < 4; ++mt)
        #pragma unroll
        for (int nt = 0; nt < 6; ++nt)
            #pragma unroll
            for (int r = 0; r < 4; ++r) acc[mt][nt][r] = 0.0f;

    if (tid == 0) {
        #pragma unroll
        for (int s = 0; s < NSTAGE; ++s) {
            mbar_init(smb + s * 8, 1);              // full[s] (expect_tx)
            mbar_init(smb + 64 + s * 8, NTHREADS);  // empty[s]
        }
    }
    __syncthreads();

    auto issue = [&](int cc, int s) {
        const uint32_t mb = smb + s * 8;
        const uint32_t st = smb + STAGE_BASE + s * STAGE_SZ;
        const int i0 = cc * KC;
        mbar_expect_tx(mb, CHUNK_TX);
        tma3(st, &tmA, i0, n, m0, mb);               // A [32 i][1 n][128 m] SW128
        #pragma unroll
        for (int ob = 0; ob < 3; ++ob)               // B [40 o][32 i] unswizzled
            tma3(st + A_SZ + ob * B_BLK, &tmB, o_cta + ob * 32, i0, kn, mb);
    };

    if (tid == 0) { issue(0, 0); issue(1, 1); }

    int cs = 0, cp = 0;          // consumer stage / phase
    int ps = 2, pp = 0;          // producer stage / phase

    // B per-thread base: row tg (160B/row), col gid
    const uint32_t bThr = (uint32_t)(tg * 160 + gid * 4);

    for (int c = 0; c < NCHUNK; ++c) {
        if (tid == 0) {
            const int cc = c + NSTAGE - 1;
            if (cc < NCHUNK) {
                if (cc >= NSTAGE)
                    mbar_wait(smb + 64 + ps * 8, (uint32_t)((pp + 1) & 1));
                issue(cc, ps);
                if (++ps == NSTAGE) { ps = 0; pp ^= 1; }
            }
        }
        mbar_wait(smb + cs * 8, (uint32_t)cp);

        const char* sa  = sm + STAGE_BASE + cs * STAGE_SZ;
        const char* sbb = sa + A_SZ;

        #pragma unroll
        for (int ks = 0; ks < 4; ++ks) {
            const uint32_t i4 = (uint32_t)(ks * 32 + tg * 4);
            uint32_t af[4][4];
            #pragma unroll
            for (int mt = 0; mt < 4; ++mt) {
                const char* p = sa + (m_base + mt * 16 + gid) * 128;
                af[mt][0] = tf32r(lds32(p + (i4 ^ mAx)));
                af[mt][1] = tf32r(lds32(p + 1024 + (i4 ^ mAx)));
                af[mt][2] = tf32r(lds32(p + ((i4 + 16) ^ mAx)));
                af[mt][3] = tf32r(lds32(p + 1024 + ((i4 + 16) ^ mAx)));
            }
            #pragma unroll
            for (int nt = 0; nt < 6; ++nt) {
                const int oabs = n_base + nt * 8;          // local, [0,96)
                const char* q = sbb + (oabs >> 5) * B_BLK + ks * (8 * 160) + bThr
                              + (oabs & 31) * 4;
                const uint32_t b0 = tf32r(lds32(q));
                const uint32_t b1 = tf32r(lds32(q + 4 * 160));
                #pragma unroll
                for (int mt = 0; mt < 4; ++mt)
                    mma_tf32(acc[mt][nt],
                             af[mt][0], af[mt][1], af[mt][2], af[mt][3], b0, b1);
            }
        }
        mbar_arrive(smb + 64 + cs * 8);
        if (++cs == NSTAGE) { cs = 0; cp ^= 1; }
    }

    // ---- epilogue ----
    #pragma unroll
    for (int mt = 0; mt < 4; ++mt) {
        const size_t r0 = (size_t)(m0 + m_base + mt * 16 + gid);
        const size_t r1 = r0 + 8;
        float* ob0 = out + (((r0 * K_ + (size_t)k) * N_) + (size_t)n) * (size_t)D3_;
        float* ob1 = out + (((r1 * K_ + (size_t)k) * N_) + (size_t)n) * (size_t)D3_;
        #pragma unroll
        for (int nt = 0; nt < 6; ++nt) {
            const int col = o_cta + n_base + nt * 8 + tg * 2;
            *(float2*)(ob0 + col) = make_float2(acc[mt][nt][0], acc[mt][nt][1]);
            *(float2*)(ob1 + col) = make_float2(acc[mt][nt][2], acc[mt][nt][3]);
        }
    }
}

extern "C" void kernel_launch(void* const* d_in, const int* in_sizes, int n_in,
                              void* d_out, int out_size) {
    const float* x     = (const float*)d_in[0];
    const float* Wqkv  = (const float*)d_in[1];
    const int* perm32  = (const int*)d_in[2];
    // d_in[3] = invperm (unused)
    const int* phase   = (const int*)d_in[4];
    float* out         = (float*)d_out;

    typedef CUresult (*EncFn)(CUtensorMap*, CUtensorMapDataType, cuuint32_t, void*,
                              const cuuint64_t*, const cuuint64_t*,
                              const cuuint32_t*, const cuuint32_t*,
                              CUtensorMapInterleave, CUtensorMapSwizzle,
                              CUtensorMapL2promotion, CUtensorMapFloatOOBfill);
    EncFn enc = nullptr;
    cudaDriverEntryPointQueryResult qst;
#if CUDART_VERSION >= 12050
    cudaGetDriverEntryPointByVersion("cuTensorMapEncodeTiled", (void**)&enc,
                                     12000, cudaEnableDefault, &qst);
#else
    cudaGetDriverEntryPoint("cuTensorMapEncodeTiled", (void**)&enc,
                            cudaEnableDefault, &qst);
#endif
    CUtensorMap tmA, tmB;
    {
        cuuint64_t dims[3]    = {(cuuint64_t)IN_, (cuuint64_t)N_, (cuuint64_t)M_TOTAL};
        cuuint64_t strides[2] = {(cuuint64_t)IN_ * 4, (cuuint64_t)N_ * IN_ * 4};
        cuuint32_t box[3]     = {32, 1, (cuuint32_t)TILE_M};
        cuuint32_t es[3]      = {1, 1, 1};
        enc(&tmA, CU_TENSOR_MAP_DATA_TYPE_FLOAT32, 3, (void*)x,
            dims, strides, box, es,
            CU_TENSOR_MAP_INTERLEAVE_NONE, CU_TENSOR_MAP_SWIZZLE_128B,
            CU_TENSOR_MAP_L2_PROMOTION_L2_128B, CU_TENSOR_MAP_FLOAT_OOB_FILL_NONE);
    }
    {
        cuuint64_t dims[3]    = {(cuuint64_t)D3_, (cuuint64_t)IN_, (cuuint64_t)(K_ * N_)};
        cuuint64_t strides[2] = {(cuuint64_t)D3_ * 4, (cuuint64_t)IN_ * D3_ * 4};
        cuuint32_t box[3]     = {(cuuint32_t)B_BOX_O, 32, 1};
        cuuint32_t es[3]      = {1, 1, 1};
        enc(&tmB, CU_TENSOR_MAP_DATA_TYPE_FLOAT32, 3, (void*)Wqkv,
            dims, strides, box, es,
            CU_TENSOR_MAP_INTERLEAVE_NONE, CU_TENSOR_MAP_SWIZZLE_NONE,
            CU_TENSOR_MAP_L2_PROMOTION_L2_128B, CU_TENSOR_MAP_FLOAT_OOB_FILL_NONE);
    }

    cudaFuncSetAttribute(qkv_tma_kernel,
                         cudaFuncAttributeMaxDynamicSharedMemorySize, SMEM_TOTAL);
    dim3 grid(M_TOTAL / TILE_M, (K_ * N_) * 2);   // (16, 128)
    qkv_tma_kernel<<<grid, NTHREADS, SMEM_TOTAL>>>(perm32, phase, out, tmA, tmB);
}